// round 4
// baseline (speedup 1.0000x reference)
#include <cuda_runtime.h>
#include <cuda_bf16.h>

#define N_NODESC 50000
#define N_EDGESC 400000

typedef unsigned int u32;
typedef unsigned long long u64;

// ---------------- device scratch ----------------
__device__ u64   g_xs[(size_t)N_NODESC * 64];     // x split: [row][pair] (hi|lo packed)
__device__ float g_Aarr[(size_t)N_NODESC * 256];  // A-half of edge pre-act (+b_edge)
__device__ float g_Barr[(size_t)N_NODESC * 256];  // B-half (gathered randomly; L2-resident)
__device__ u64   g_nas[(size_t)N_NODESC * 64];    // node_agg split (128 elems -> 64 pairs)
__device__ u64   g_eas[(size_t)N_NODESC * 128];   // edge_agg split (256 -> 128 pairs)
__device__ u64   g_hs[(size_t)N_NODESC * 192];    // h split (384 -> 192 pairs)
__device__ float g_h2[(size_t)N_NODESC * 32];
__device__ u64   g_Wcs[64 * 512];                 // Wc split  [pair][n]
__device__ u64   g_Wns[64 * 256];                 // W_node split
__device__ u64   g_Wes[128 * 128];                // W_ed split
__device__ u64   g_Wfs[192 * 32];                 // W_f1 split
__device__ float g_bc[512];
__device__ int   g_count[N_NODESC];
__device__ int   g_off[N_NODESC + 1];
__device__ int   g_cur[N_NODESC];
__device__ int   g_csr[N_EDGESC];
__device__ int   g_ei32[2 * N_EDGESC];
__device__ int   g_dtype_flag;

// ---------------- bf16 hi/lo split helpers ----------------
__device__ __forceinline__ u64 splitpair(float a, float b) {
    __nv_bfloat162 h = __float22bfloat162_rn(make_float2(a, b));
    float2 hf = __bfloat1622float2(h);
    __nv_bfloat162 l = __float22bfloat162_rn(make_float2(a - hf.x, b - hf.y));
    u32 hw = *(u32*)&h, lw = *(u32*)&l;
    return (u64)hw | ((u64)lw << 32);
}

__device__ __forceinline__ void mma16816(float* d, const u32* a, const u32* b) {
    asm volatile(
        "mma.sync.aligned.m16n8k16.row.col.f32.bf16.bf16.f32 "
        "{%0,%1,%2,%3}, {%4,%5,%6,%7}, {%8,%9}, {%0,%1,%2,%3};\n"
        : "+f"(d[0]), "+f"(d[1]), "+f"(d[2]), "+f"(d[3])
        : "r"(a[0]), "r"(a[1]), "r"(a[2]), "r"(a[3]), "r"(b[0]), "r"(b[1]));
}

// ---------------- init / dtype detect / convert+hist ----------------
__global__ void zero_init_kernel() {
    int i = blockIdx.x * blockDim.x + threadIdx.x;
    if (i < N_NODESC) g_count[i] = 0;
    if (i == 0) g_dtype_flag = 0;
}

__global__ void detect_kernel(const int* __restrict__ w) {
    int acc = 0;
    for (int i = blockIdx.x * blockDim.x + threadIdx.x; i < N_EDGESC; i += gridDim.x * blockDim.x)
        acc |= w[2 * i + 1];
    #pragma unroll
    for (int o = 16; o; o >>= 1) acc |= __shfl_xor_sync(0xffffffffu, acc, o);
    if ((threadIdx.x & 31) == 0 && acc) atomicOr(&g_dtype_flag, 1);
}

__global__ void conv_hist_kernel(const void* __restrict__ ei) {
    int e = blockIdx.x * blockDim.x + threadIdx.x;
    if (e < N_EDGESC) {
        int s, d;
        if (g_dtype_flag) {
            s = ((const int*)ei)[e];
            d = ((const int*)ei)[N_EDGESC + e];
        } else {
            s = (int)((const long long*)ei)[e];
            d = (int)((const long long*)ei)[N_EDGESC + e];
        }
        g_ei32[e] = s;
        g_ei32[N_EDGESC + e] = d;
        atomicAdd(&g_count[d], 1);
    }
}

// ---------------- CSR scan + scatter ----------------
__global__ void scan_kernel() {
    __shared__ int wsum[33];
    __shared__ int carry;
    int tid = threadIdx.x, lane = tid & 31, w = tid >> 5;
    if (tid == 0) carry = 0;
    __syncthreads();
    for (int base = 0; base < N_NODESC; base += 1024) {
        int i = base + tid;
        int orig = (i < N_NODESC) ? g_count[i] : 0;
        int v = orig;
        #pragma unroll
        for (int o = 1; o < 32; o <<= 1) {
            int t = __shfl_up_sync(0xffffffffu, v, o);
            if (lane >= o) v += t;
        }
        if (lane == 31) wsum[w] = v;
        __syncthreads();
        if (w == 0) {
            int s = wsum[lane], sv = s;
            #pragma unroll
            for (int o = 1; o < 32; o <<= 1) {
                int t = __shfl_up_sync(0xffffffffu, sv, o);
                if (lane >= o) sv += t;
            }
            wsum[lane] = sv - s;
            if (lane == 31) wsum[32] = sv;
        }
        __syncthreads();
        if (i < N_NODESC) {
            int ex = carry + wsum[w] + v - orig;
            g_off[i] = ex;
            g_cur[i] = ex;
        }
        __syncthreads();
        if (tid == 0) carry += wsum[32];
        __syncthreads();
    }
    if (tid == 0) g_off[N_NODESC] = carry;
}

__global__ void scatter_kernel() {
    int e = blockIdx.x * blockDim.x + threadIdx.x;
    if (e < N_EDGESC) {
        int d = g_ei32[N_EDGESC + e];
        int s = g_ei32[e];
        int p = atomicAdd(&g_cur[d], 1);
        g_csr[p] = s;
    }
}

// ---------------- weight prep: split all weights into packed hi|lo pairs ----------------
__device__ __forceinline__ float wcval(const float* We, int k, int n) {
    return (n < 256) ? (We[k * 256 + n] - We[(128 + k) * 256 + n])
                     : We[(128 + k) * 256 + (n - 256)];
}

__global__ void prep_w_kernel(const float* __restrict__ We, const float* __restrict__ be,
                              const float* __restrict__ Wn, const float* __restrict__ Wd,
                              const float* __restrict__ Wf) {
    int idx = blockIdx.x * blockDim.x + threadIdx.x;   // 0 .. 32767
    {   // Wc: 64 pairs x 512
        int c = idx >> 9, n = idx & 511;
        g_Wcs[idx] = splitpair(wcval(We, 2 * c, n), wcval(We, 2 * c + 1, n));
    }
    if (idx < 64 * 256) {
        int c = idx >> 8, n = idx & 255;
        g_Wns[idx] = splitpair(Wn[2 * c * 256 + n], Wn[(2 * c + 1) * 256 + n]);
    }
    if (idx < 128 * 128) {
        int c = idx >> 7, n = idx & 127;
        g_Wes[idx] = splitpair(Wd[2 * c * 128 + n], Wd[(2 * c + 1) * 128 + n]);
    }
    if (idx < 192 * 32) {
        int c = idx >> 5, n = idx & 31;
        g_Wfs[idx] = splitpair(Wf[2 * c * 32 + n], Wf[(2 * c + 1) * 32 + n]);
    }
    if (idx < 512) g_bc[idx] = (idx < 256) ? be[idx] : 0.0f;
}

__global__ void split_x_kernel(const float* __restrict__ x) {
    int idx = blockIdx.x * blockDim.x + threadIdx.x;
    if (idx < N_NODESC * 64) {
        int row = idx >> 6, c = idx & 63;
        float2 v = *(const float2*)(x + (size_t)row * 128 + 2 * c);
        g_xs[idx] = splitpair(v.x, v.y);
    }
}

// ---------------- tensor-core GEMM on pre-split operands ----------------
// out = act(A[M,K] @ W[K,N] + bias); A,W packed (hi|lo) bf16x2 pairs.
// OMODE: 0 = fp32 out, 1 = split-u64 out, 2 = AB dual fp32 (Aarr / Barr)
template <int BM, int BN, int WM, int WN, bool RELU, int OMODE>
__global__ __launch_bounds__(256) void mma_gemm(
    const u64* __restrict__ As,      // [M][K/2]
    const u64* __restrict__ Ws,      // [K/2][Nfull]
    const float* __restrict__ bias,
    float* __restrict__ outf, u64* __restrict__ outs, float* __restrict__ outf2,
    int ldo_p, int ocol0, int M, int K, int Nfull)
{
    constexpr int PC = 16;                      // pairs per stage (KC = 32)
    constexpr int WARPS_N = BN / WN;
    constexpr int MT = WM / 16, NT = WN / 8;
    __shared__ u32 Ah[BM][17], Al[BM][17];
    __shared__ u32 Wh[BN][17], Wl[BN][17];

    int tid = threadIdx.x;
    int w = tid >> 5, lane = tid & 31;
    int gr = lane >> 2, thc = lane & 3;
    int wm = w / WARPS_N, wn = w % WARPS_N;
    int m0 = blockIdx.y * BM, n0 = blockIdx.x * BN;
    int m0w = wm * WM, n0w = wn * WN;
    int Kp = K >> 1;

    float d[MT][NT][4];
    #pragma unroll
    for (int i = 0; i < MT; i++)
        #pragma unroll
        for (int j = 0; j < NT; j++)
            #pragma unroll
            for (int q = 0; q < 4; q++) d[i][j][q] = 0.0f;

    for (int p0 = 0; p0 < Kp; p0 += PC) {
        // A tile: BM x 16 pairs
        #pragma unroll
        for (int j = 0; j < (BM * PC) / 256; j++) {
            int p = tid + j * 256;
            int row = p >> 4, c = p & 15;
            u64 v = 0;
            if (m0 + row < M) v = As[(size_t)(m0 + row) * Kp + p0 + c];
            Ah[row][c] = (u32)v;
            Al[row][c] = (u32)(v >> 32);
        }
        // W tile: BN x 16 pairs (n fastest for coalescing)
        #pragma unroll
        for (int j = 0; j < (BN * PC + 255) / 256; j++) {
            int p = tid + j * 256;
            if (p < BN * PC) {
                int n = p % BN, c = p / BN;
                u64 v = Ws[(size_t)(p0 + c) * Nfull + n0 + n];
                Wh[n][c] = (u32)v;
                Wl[n][c] = (u32)(v >> 32);
            }
        }
        __syncthreads();

        #pragma unroll
        for (int s = 0; s < 2; s++) {
            int cb = 8 * s;
            u32 ah[MT][4], al[MT][4], bh[NT][2], bl[NT][2];
            #pragma unroll
            for (int i = 0; i < MT; i++) {
                int r0 = m0w + 16 * i + gr, r1 = r0 + 8;
                ah[i][0] = Ah[r0][cb + thc];     ah[i][1] = Ah[r1][cb + thc];
                ah[i][2] = Ah[r0][cb + thc + 4]; ah[i][3] = Ah[r1][cb + thc + 4];
                al[i][0] = Al[r0][cb + thc];     al[i][1] = Al[r1][cb + thc];
                al[i][2] = Al[r0][cb + thc + 4]; al[i][3] = Al[r1][cb + thc + 4];
            }
            #pragma unroll
            for (int j = 0; j < NT; j++) {
                int nn = n0w + 8 * j + gr;
                bh[j][0] = Wh[nn][cb + thc]; bh[j][1] = Wh[nn][cb + thc + 4];
                bl[j][0] = Wl[nn][cb + thc]; bl[j][1] = Wl[nn][cb + thc + 4];
            }
            #pragma unroll
            for (int i = 0; i < MT; i++)
                #pragma unroll
                for (int j = 0; j < NT; j++) {
                    mma16816(d[i][j], ah[i], bh[j]);
                    mma16816(d[i][j], ah[i], bl[j]);
                    mma16816(d[i][j], al[i], bh[j]);
                }
        }
        __syncthreads();
    }

    // epilogue
    #pragma unroll
    for (int i = 0; i < MT; i++) {
        int row0 = m0 + m0w + 16 * i + gr;
        int row1 = row0 + 8;
        #pragma unroll
        for (int j = 0; j < NT; j++) {
            int col = n0 + n0w + 8 * j + 2 * thc;
            float b0 = bias[col], b1 = bias[col + 1];
            float v00 = d[i][j][0] + b0, v01 = d[i][j][1] + b1;
            float v10 = d[i][j][2] + b0, v11 = d[i][j][3] + b1;
            if (RELU) {
                v00 = fmaxf(v00, 0.0f); v01 = fmaxf(v01, 0.0f);
                v10 = fmaxf(v10, 0.0f); v11 = fmaxf(v11, 0.0f);
            }
            if (OMODE == 0) {
                if (row0 < M) *(float2*)(outf + (size_t)row0 * ldo_p + col) = make_float2(v00, v01);
                if (row1 < M) *(float2*)(outf + (size_t)row1 * ldo_p + col) = make_float2(v10, v11);
            } else if (OMODE == 1) {
                int pidx = (ocol0 + col) >> 1;
                if (row0 < M) outs[(size_t)row0 * ldo_p + pidx] = splitpair(v00, v01);
                if (row1 < M) outs[(size_t)row1 * ldo_p + pidx] = splitpair(v10, v11);
            } else {   // AB dual fp32
                float* dst = (col < 256) ? outf : outf2;
                int cc = (col < 256) ? col : col - 256;
                if (row0 < M) *(float2*)(dst + (size_t)row0 * 256 + cc) = make_float2(v00, v01);
                if (row1 < M) *(float2*)(dst + (size_t)row1 * 256 + cc) = make_float2(v10, v11);
            }
        }
    }
}

// ---------------- per-dst aggregation: na = sum x[src]; ea = sum relu(A[dst]+B[src]) ----------------
__global__ void aggregate_kernel(const float* __restrict__ x) {
    int gw = (blockIdx.x * blockDim.x + threadIdx.x) >> 5;
    int lane = threadIdx.x & 31;
    if (gw >= N_NODESC) return;
    int beg = g_off[gw], end = g_off[gw + 1];
    const float4* Ar = (const float4*)(g_Aarr + (size_t)gw * 256);
    float4 a0 = Ar[lane], a1 = Ar[32 + lane];
    float4 na = make_float4(0, 0, 0, 0);
    float4 e0 = na, e1 = na;
    for (int e = beg; e < end; e++) {
        int s = g_csr[e];
        float4 xv = ((const float4*)(x + (size_t)s * 128))[lane];
        const float4* br = (const float4*)(g_Barr + (size_t)s * 256);
        float4 b0 = br[lane], b1 = br[32 + lane];
        na.x += xv.x; na.y += xv.y; na.z += xv.z; na.w += xv.w;
        e0.x += fmaxf(a0.x + b0.x, 0.0f);
        e0.y += fmaxf(a0.y + b0.y, 0.0f);
        e0.z += fmaxf(a0.z + b0.z, 0.0f);
        e0.w += fmaxf(a0.w + b0.w, 0.0f);
        e1.x += fmaxf(a1.x + b1.x, 0.0f);
        e1.y += fmaxf(a1.y + b1.y, 0.0f);
        e1.z += fmaxf(a1.z + b1.z, 0.0f);
        e1.w += fmaxf(a1.w + b1.w, 0.0f);
    }
    // write outputs pre-split for the downstream GEMMs
    u64* nw = g_nas + (size_t)gw * 64;
    nw[2 * lane]     = splitpair(na.x, na.y);
    nw[2 * lane + 1] = splitpair(na.z, na.w);
    u64* ew = g_eas + (size_t)gw * 128;
    ew[2 * lane]          = splitpair(e0.x, e0.y);
    ew[2 * lane + 1]      = splitpair(e0.z, e0.w);
    ew[64 + 2 * lane]     = splitpair(e1.x, e1.y);
    ew[64 + 2 * lane + 1] = splitpair(e1.z, e1.w);
}

// ---------------- final: out = sigmoid(h2 @ W_f2 + b_f2) ----------------
__global__ void sigmoid_kernel(const float* __restrict__ Wf2, const float* __restrict__ bf2,
                               float* __restrict__ out) {
    int gw = (blockIdx.x * blockDim.x + threadIdx.x) >> 5;
    int lane = threadIdx.x & 31;
    if (gw >= N_NODESC) return;
    float t = g_h2[(size_t)gw * 32 + lane] * Wf2[lane];
    #pragma unroll
    for (int o = 16; o; o >>= 1) t += __shfl_xor_sync(0xffffffffu, t, o);
    if (lane == 0) out[gw] = 1.0f / (1.0f + __expf(-(t + bf2[0])));
}

// ---------------- launch ----------------
extern "C" void kernel_launch(void* const* d_in, const int* in_sizes, int n_in,
                              void* d_out, int out_size) {
    const float* x  = (const float*)d_in[0];
    const void*  ei = d_in[1];
    const float* W_node = (const float*)d_in[3];
    const float* b_node = (const float*)d_in[4];
    const float* W_edge = (const float*)d_in[5];
    const float* b_edge = (const float*)d_in[6];
    const float* W_ed   = (const float*)d_in[7];
    const float* b_ed   = (const float*)d_in[8];
    const float* W_f1   = (const float*)d_in[9];
    const float* b_f1   = (const float*)d_in[10];
    const float* W_f2   = (const float*)d_in[11];
    const float* b_f2   = (const float*)d_in[12];
    float* out = (float*)d_out;

    u64 *pxs, *pnas, *peas, *phs, *pWcs, *pWns, *pWes, *pWfs;
    float *pA, *pB, *pbc, *ph2;
    cudaGetSymbolAddress((void**)&pxs,  g_xs);
    cudaGetSymbolAddress((void**)&pnas, g_nas);
    cudaGetSymbolAddress((void**)&peas, g_eas);
    cudaGetSymbolAddress((void**)&phs,  g_hs);
    cudaGetSymbolAddress((void**)&pWcs, g_Wcs);
    cudaGetSymbolAddress((void**)&pWns, g_Wns);
    cudaGetSymbolAddress((void**)&pWes, g_Wes);
    cudaGetSymbolAddress((void**)&pWfs, g_Wfs);
    cudaGetSymbolAddress((void**)&pA,   g_Aarr);
    cudaGetSymbolAddress((void**)&pB,   g_Barr);
    cudaGetSymbolAddress((void**)&pbc,  g_bc);
    cudaGetSymbolAddress((void**)&ph2,  g_h2);

    const int MB = (N_NODESC + 127) / 128;   // 391

    zero_init_kernel<<<(N_NODESC + 255) / 256, 256>>>();
    detect_kernel<<<256, 256>>>((const int*)ei);
    conv_hist_kernel<<<(N_EDGESC + 255) / 256, 256>>>(ei);
    scan_kernel<<<1, 1024>>>();
    scatter_kernel<<<(N_EDGESC + 255) / 256, 256>>>();

    prep_w_kernel<<<128, 256>>>(W_edge, b_edge, W_node, W_ed, W_f1);
    split_x_kernel<<<(N_NODESC * 64 + 255) / 256, 256>>>(x);

    // AB = x @ Wc  -> Aarr (bias folded) / Barr, fp32
    mma_gemm<128, 64, 32, 32, false, 2><<<dim3(8, MB), 256>>>(
        pxs, pWcs, pbc, pA, (u64*)0, pB, 0, 0, N_NODESC, 128, 512);

    aggregate_kernel<<<(N_NODESC + 7) / 8, 256>>>(x);

    // nodes -> h[:,0:256) split ; edges -> h[:,256:384) split
    mma_gemm<128, 64, 32, 32, true, 1><<<dim3(4, MB), 256>>>(
        pnas, pWns, b_node, (float*)0, phs, (float*)0, 192, 0, N_NODESC, 128, 256);
    mma_gemm<128, 64, 32, 32, true, 1><<<dim3(2, MB), 256>>>(
        peas, pWes, b_ed, (float*)0, phs, (float*)0, 192, 256, N_NODESC, 256, 128);

    // h2 = relu(h @ W_f1 + b_f1), fp32
    mma_gemm<128, 32, 32, 16, true, 0><<<dim3(1, MB), 256>>>(
        phs, pWfs, b_f1, ph2, (u64*)0, (float*)0, 32, 0, N_NODESC, 384, 32);

    sigmoid_kernel<<<(N_NODESC + 7) / 8, 256>>>(W_f2, b_f2, out);
}

// round 5
// speedup vs baseline: 1.1062x; 1.1062x over previous
#include <cuda_runtime.h>
#include <cuda_bf16.h>

#define N_NODESC 50000
#define N_EDGESC 400000
#define SCAN_BLKS 49   // ceil(50000/1024)

typedef unsigned int u32;
typedef unsigned long long u64;

// ---------------- device scratch ----------------
__device__ u64   g_xs[(size_t)N_NODESC * 64];     // x split: [row][pair] (hi|lo packed)
__device__ float g_Aarr[(size_t)N_NODESC * 256];  // A-half of edge pre-act (+b_edge)
__device__ float g_Barr[(size_t)N_NODESC * 256];  // B-half (gathered randomly; L2-resident)
__device__ u64   g_nas[(size_t)N_NODESC * 64];    // node_agg split (128 elems -> 64 pairs)
__device__ u64   g_eas[(size_t)N_NODESC * 128];   // edge_agg split (256 -> 128 pairs)
__device__ u64   g_hs[(size_t)N_NODESC * 192];    // h split (384 -> 192 pairs)
__device__ float g_h2[(size_t)N_NODESC * 32];
__device__ u64   g_Wcs[64 * 512];                 // Wc split  [pair][n]
__device__ u64   g_Wns[64 * 256];                 // W_node split
__device__ u64   g_Wes[128 * 128];                // W_ed split
__device__ u64   g_Wfs[192 * 32];                 // W_f1 split
__device__ float g_bc[512];
__device__ int   g_count[N_NODESC];
__device__ int   g_off[N_NODESC + 1];
__device__ int   g_cur[N_NODESC];
__device__ int   g_csr[N_EDGESC];
__device__ int   g_ei32[2 * N_EDGESC];
__device__ int   g_bsum[SCAN_BLKS];
__device__ int   g_bpre[SCAN_BLKS];
__device__ int   g_dtype_flag;

// ---------------- bf16 hi/lo split helpers ----------------
__device__ __forceinline__ u64 splitpair(float a, float b) {
    __nv_bfloat162 h = __float22bfloat162_rn(make_float2(a, b));
    float2 hf = __bfloat1622float2(h);
    __nv_bfloat162 l = __float22bfloat162_rn(make_float2(a - hf.x, b - hf.y));
    u32 hw = *(u32*)&h, lw = *(u32*)&l;
    return (u64)hw | ((u64)lw << 32);
}

__device__ __forceinline__ void mma16816(float* d, const u32* a, const u32* b) {
    asm volatile(
        "mma.sync.aligned.m16n8k16.row.col.f32.bf16.bf16.f32 "
        "{%0,%1,%2,%3}, {%4,%5,%6,%7}, {%8,%9}, {%0,%1,%2,%3};\n"
        : "+f"(d[0]), "+f"(d[1]), "+f"(d[2]), "+f"(d[3])
        : "r"(a[0]), "r"(a[1]), "r"(a[2]), "r"(a[3]), "r"(b[0]), "r"(b[1]));
}

// ---------------- init / dtype detect / convert+hist ----------------
__global__ void zero_init_kernel() {
    int i = blockIdx.x * blockDim.x + threadIdx.x;
    if (i < N_NODESC) g_count[i] = 0;
    if (i == 0) g_dtype_flag = 0;
}

__global__ void detect_kernel(const int* __restrict__ w) {
    int acc = 0;
    for (int i = blockIdx.x * blockDim.x + threadIdx.x; i < N_EDGESC; i += gridDim.x * blockDim.x)
        acc |= w[2 * i + 1];
    #pragma unroll
    for (int o = 16; o; o >>= 1) acc |= __shfl_xor_sync(0xffffffffu, acc, o);
    if ((threadIdx.x & 31) == 0 && acc) atomicOr(&g_dtype_flag, 1);
}

__global__ void conv_hist_kernel(const void* __restrict__ ei) {
    int e = blockIdx.x * blockDim.x + threadIdx.x;
    if (e < N_EDGESC) {
        int s, d;
        if (g_dtype_flag) {
            s = ((const int*)ei)[e];
            d = ((const int*)ei)[N_EDGESC + e];
        } else {
            s = (int)((const long long*)ei)[e];
            d = (int)((const long long*)ei)[N_EDGESC + e];
        }
        g_ei32[e] = s;
        g_ei32[N_EDGESC + e] = d;
        atomicAdd(&g_count[d], 1);
    }
}

// ---------------- parallel scan: local scan -> block-sum scan -> offset add ----------------
__global__ void scan1_kernel() {
    __shared__ int wsum[32], wpre[32];
    int tid = threadIdx.x, lane = tid & 31, w = tid >> 5;
    int i = blockIdx.x * 1024 + tid;
    int orig = (i < N_NODESC) ? g_count[i] : 0;
    int v = orig;
    #pragma unroll
    for (int o = 1; o < 32; o <<= 1) {
        int t = __shfl_up_sync(0xffffffffu, v, o);
        if (lane >= o) v += t;
    }
    if (lane == 31) wsum[w] = v;
    __syncthreads();
    if (w == 0) {
        int s = wsum[lane], sv = s;
        #pragma unroll
        for (int o = 1; o < 32; o <<= 1) {
            int t = __shfl_up_sync(0xffffffffu, sv, o);
            if (lane >= o) sv += t;
        }
        wpre[lane] = sv - s;
        if (lane == 31) g_bsum[blockIdx.x] = sv;
    }
    __syncthreads();
    if (i < N_NODESC) {
        int ex = wpre[w] + v - orig;   // exclusive prefix within block
        g_off[i] = ex;
        g_cur[i] = ex;
    }
}

__global__ void scan2_kernel() {
    __shared__ int s[64];
    int tid = threadIdx.x;
    int orig = (tid < SCAN_BLKS) ? g_bsum[tid] : 0;
    s[tid] = orig;
    __syncthreads();
    #pragma unroll
    for (int o = 1; o < 64; o <<= 1) {
        int t = (tid >= o) ? s[tid - o] : 0;
        __syncthreads();
        s[tid] += t;
        __syncthreads();
    }
    if (tid < SCAN_BLKS) g_bpre[tid] = s[tid] - orig;
    if (tid == 63) g_off[N_NODESC] = s[63];
}

__global__ void scan3_kernel() {
    int i = blockIdx.x * blockDim.x + threadIdx.x;
    if (i < N_NODESC) {
        int add = g_bpre[i >> 10];
        g_off[i] += add;
        g_cur[i] += add;
    }
}

__global__ void scatter_kernel() {
    int e = blockIdx.x * blockDim.x + threadIdx.x;
    if (e < N_EDGESC) {
        int d = g_ei32[N_EDGESC + e];
        int s = g_ei32[e];
        int p = atomicAdd(&g_cur[d], 1);
        g_csr[p] = s;
    }
}

// ---------------- weight prep: split all weights into packed hi|lo pairs ----------------
__device__ __forceinline__ float wcval(const float* We, int k, int n) {
    return (n < 256) ? (We[k * 256 + n] - We[(128 + k) * 256 + n])
                     : We[(128 + k) * 256 + (n - 256)];
}

__global__ void prep_w_kernel(const float* __restrict__ We, const float* __restrict__ be,
                              const float* __restrict__ Wn, const float* __restrict__ Wd,
                              const float* __restrict__ Wf) {
    int idx = blockIdx.x * blockDim.x + threadIdx.x;   // 0 .. 32767
    {   // Wc: 64 pairs x 512
        int c = idx >> 9, n = idx & 511;
        g_Wcs[idx] = splitpair(wcval(We, 2 * c, n), wcval(We, 2 * c + 1, n));
    }
    if (idx < 64 * 256) {
        int c = idx >> 8, n = idx & 255;
        g_Wns[idx] = splitpair(Wn[2 * c * 256 + n], Wn[(2 * c + 1) * 256 + n]);
    }
    if (idx < 128 * 128) {
        int c = idx >> 7, n = idx & 127;
        g_Wes[idx] = splitpair(Wd[2 * c * 128 + n], Wd[(2 * c + 1) * 128 + n]);
    }
    if (idx < 192 * 32) {
        int c = idx >> 5, n = idx & 31;
        g_Wfs[idx] = splitpair(Wf[2 * c * 32 + n], Wf[(2 * c + 1) * 32 + n]);
    }
    if (idx < 512) g_bc[idx] = (idx < 256) ? be[idx] : 0.0f;
}

__global__ void split_x_kernel(const float* __restrict__ x) {
    int idx = blockIdx.x * blockDim.x + threadIdx.x;
    if (idx < N_NODESC * 64) {
        int row = idx >> 6, c = idx & 63;
        float2 v = *(const float2*)(x + (size_t)row * 128 + 2 * c);
        g_xs[idx] = splitpair(v.x, v.y);
    }
}

// ---------------- tensor-core GEMM on pre-split operands ----------------
// Row stride 20 words: fragment LDS addr = gr*20 + cb + thc; gr*20 mod 32 =
// {0,20,8,28,16,4,24,12} + thc{0..3} -> 32 distinct banks (cb=0 and cb=8).
// OMODE: 0 = fp32 out, 1 = split-u64 out, 2 = AB dual fp32 (Aarr / Barr)
template <int BM, int BN, int WM, int WN, bool RELU, int OMODE>
__global__ __launch_bounds__(256) void mma_gemm(
    const u64* __restrict__ As,      // [M][K/2]
    const u64* __restrict__ Ws,      // [K/2][Nfull]
    const float* __restrict__ bias,
    float* __restrict__ outf, u64* __restrict__ outs, float* __restrict__ outf2,
    int ldo_p, int ocol0, int M, int K, int Nfull)
{
    constexpr int PC = 16;                      // pairs per stage (KC = 32)
    constexpr int SR = 20;                      // smem row stride (conflict-free)
    constexpr int WARPS_N = BN / WN;
    constexpr int MT = WM / 16, NT = WN / 8;
    __shared__ u32 Ah[BM][SR], Al[BM][SR];
    __shared__ u32 Wh[BN][SR], Wl[BN][SR];

    int tid = threadIdx.x;
    int w = tid >> 5, lane = tid & 31;
    int gr = lane >> 2, thc = lane & 3;
    int wm = w / WARPS_N, wn = w % WARPS_N;
    int m0 = blockIdx.y * BM, n0 = blockIdx.x * BN;
    int m0w = wm * WM, n0w = wn * WN;
    int Kp = K >> 1;

    float d[MT][NT][4];
    #pragma unroll
    for (int i = 0; i < MT; i++)
        #pragma unroll
        for (int j = 0; j < NT; j++)
            #pragma unroll
            for (int q = 0; q < 4; q++) d[i][j][q] = 0.0f;

    for (int p0 = 0; p0 < Kp; p0 += PC) {
        // A tile: BM x 16 pairs
        #pragma unroll
        for (int j = 0; j < (BM * PC) / 256; j++) {
            int p = tid + j * 256;
            int row = p >> 4, c = p & 15;
            u64 v = 0;
            if (m0 + row < M) v = As[(size_t)(m0 + row) * Kp + p0 + c];
            Ah[row][c] = (u32)v;
            Al[row][c] = (u32)(v >> 32);
        }
        // W tile: BN x 16 pairs (n fastest for coalescing)
        #pragma unroll
        for (int j = 0; j < (BN * PC + 255) / 256; j++) {
            int p = tid + j * 256;
            if (p < BN * PC) {
                int n = p % BN, c = p / BN;
                u64 v = Ws[(size_t)(p0 + c) * Nfull + n0 + n];
                Wh[n][c] = (u32)v;
                Wl[n][c] = (u32)(v >> 32);
            }
        }
        __syncthreads();

        #pragma unroll
        for (int s = 0; s < 2; s++) {
            int cb = 8 * s;
            u32 ah[MT][4], al[MT][4], bh[NT][2], bl[NT][2];
            #pragma unroll
            for (int i = 0; i < MT; i++) {
                int r0 = m0w + 16 * i + gr, r1 = r0 + 8;
                ah[i][0] = Ah[r0][cb + thc];     ah[i][1] = Ah[r1][cb + thc];
                ah[i][2] = Ah[r0][cb + thc + 4]; ah[i][3] = Ah[r1][cb + thc + 4];
                al[i][0] = Al[r0][cb + thc];     al[i][1] = Al[r1][cb + thc];
                al[i][2] = Al[r0][cb + thc + 4]; al[i][3] = Al[r1][cb + thc + 4];
            }
            #pragma unroll
            for (int j = 0; j < NT; j++) {
                int nn = n0w + 8 * j + gr;
                bh[j][0] = Wh[nn][cb + thc]; bh[j][1] = Wh[nn][cb + thc + 4];
                bl[j][0] = Wl[nn][cb + thc]; bl[j][1] = Wl[nn][cb + thc + 4];
            }
            #pragma unroll
            for (int i = 0; i < MT; i++)
                #pragma unroll
                for (int j = 0; j < NT; j++) {
                    mma16816(d[i][j], ah[i], bh[j]);
                    mma16816(d[i][j], ah[i], bl[j]);
                    mma16816(d[i][j], al[i], bh[j]);
                }
        }
        __syncthreads();
    }

    // epilogue
    #pragma unroll
    for (int i = 0; i < MT; i++) {
        int row0 = m0 + m0w + 16 * i + gr;
        int row1 = row0 + 8;
        #pragma unroll
        for (int j = 0; j < NT; j++) {
            int col = n0 + n0w + 8 * j + 2 * thc;
            float b0 = bias[col], b1 = bias[col + 1];
            float v00 = d[i][j][0] + b0, v01 = d[i][j][1] + b1;
            float v10 = d[i][j][2] + b0, v11 = d[i][j][3] + b1;
            if (RELU) {
                v00 = fmaxf(v00, 0.0f); v01 = fmaxf(v01, 0.0f);
                v10 = fmaxf(v10, 0.0f); v11 = fmaxf(v11, 0.0f);
            }
            if (OMODE == 0) {
                if (row0 < M) *(float2*)(outf + (size_t)row0 * ldo_p + col) = make_float2(v00, v01);
                if (row1 < M) *(float2*)(outf + (size_t)row1 * ldo_p + col) = make_float2(v10, v11);
            } else if (OMODE == 1) {
                int pidx = (ocol0 + col) >> 1;
                if (row0 < M) outs[(size_t)row0 * ldo_p + pidx] = splitpair(v00, v01);
                if (row1 < M) outs[(size_t)row1 * ldo_p + pidx] = splitpair(v10, v11);
            } else {   // AB dual fp32
                float* dst = (col < 256) ? outf : outf2;
                int cc = (col < 256) ? col : col - 256;
                if (row0 < M) *(float2*)(dst + (size_t)row0 * 256 + cc) = make_float2(v00, v01);
                if (row1 < M) *(float2*)(dst + (size_t)row1 * 256 + cc) = make_float2(v10, v11);
            }
        }
    }
}

// ---------------- per-dst aggregation: na = sum x[src]; ea = sum relu(A[dst]+B[src]) ----------------
__global__ void aggregate_kernel(const float* __restrict__ x) {
    int gw = (blockIdx.x * blockDim.x + threadIdx.x) >> 5;
    int lane = threadIdx.x & 31;
    if (gw >= N_NODESC) return;
    int beg = g_off[gw], end = g_off[gw + 1];
    const float4* Ar = (const float4*)(g_Aarr + (size_t)gw * 256);
    float4 a0 = Ar[lane], a1 = Ar[32 + lane];
    float4 na = make_float4(0, 0, 0, 0);
    float4 e0 = na, e1 = na;
    for (int e = beg; e < end; e++) {
        int s = g_csr[e];
        float4 xv = ((const float4*)(x + (size_t)s * 128))[lane];
        const float4* br = (const float4*)(g_Barr + (size_t)s * 256);
        float4 b0 = br[lane], b1 = br[32 + lane];
        na.x += xv.x; na.y += xv.y; na.z += xv.z; na.w += xv.w;
        e0.x += fmaxf(a0.x + b0.x, 0.0f);
        e0.y += fmaxf(a0.y + b0.y, 0.0f);
        e0.z += fmaxf(a0.z + b0.z, 0.0f);
        e0.w += fmaxf(a0.w + b0.w, 0.0f);
        e1.x += fmaxf(a1.x + b1.x, 0.0f);
        e1.y += fmaxf(a1.y + b1.y, 0.0f);
        e1.z += fmaxf(a1.z + b1.z, 0.0f);
        e1.w += fmaxf(a1.w + b1.w, 0.0f);
    }
    // write outputs pre-split for the downstream GEMMs
    u64* nw = g_nas + (size_t)gw * 64;
    nw[2 * lane]     = splitpair(na.x, na.y);
    nw[2 * lane + 1] = splitpair(na.z, na.w);
    u64* ew = g_eas + (size_t)gw * 128;
    ew[2 * lane]          = splitpair(e0.x, e0.y);
    ew[2 * lane + 1]      = splitpair(e0.z, e0.w);
    ew[64 + 2 * lane]     = splitpair(e1.x, e1.y);
    ew[64 + 2 * lane + 1] = splitpair(e1.z, e1.w);
}

// ---------------- final: out = sigmoid(h2 @ W_f2 + b_f2) ----------------
__global__ void sigmoid_kernel(const float* __restrict__ Wf2, const float* __restrict__ bf2,
                               float* __restrict__ out) {
    int gw = (blockIdx.x * blockDim.x + threadIdx.x) >> 5;
    int lane = threadIdx.x & 31;
    if (gw >= N_NODESC) return;
    float t = g_h2[(size_t)gw * 32 + lane] * Wf2[lane];
    #pragma unroll
    for (int o = 16; o; o >>= 1) t += __shfl_xor_sync(0xffffffffu, t, o);
    if (lane == 0) out[gw] = 1.0f / (1.0f + __expf(-(t + bf2[0])));
}

// ---------------- launch ----------------
extern "C" void kernel_launch(void* const* d_in, const int* in_sizes, int n_in,
                              void* d_out, int out_size) {
    const float* x  = (const float*)d_in[0];
    const void*  ei = d_in[1];
    const float* W_node = (const float*)d_in[3];
    const float* b_node = (const float*)d_in[4];
    const float* W_edge = (const float*)d_in[5];
    const float* b_edge = (const float*)d_in[6];
    const float* W_ed   = (const float*)d_in[7];
    const float* b_ed   = (const float*)d_in[8];
    const float* W_f1   = (const float*)d_in[9];
    const float* b_f1   = (const float*)d_in[10];
    const float* W_f2   = (const float*)d_in[11];
    const float* b_f2   = (const float*)d_in[12];
    float* out = (float*)d_out;

    u64 *pxs, *pnas, *peas, *phs, *pWcs, *pWns, *pWes, *pWfs;
    float *pA, *pB, *pbc, *ph2;
    cudaGetSymbolAddress((void**)&pxs,  g_xs);
    cudaGetSymbolAddress((void**)&pnas, g_nas);
    cudaGetSymbolAddress((void**)&peas, g_eas);
    cudaGetSymbolAddress((void**)&phs,  g_hs);
    cudaGetSymbolAddress((void**)&pWcs, g_Wcs);
    cudaGetSymbolAddress((void**)&pWns, g_Wns);
    cudaGetSymbolAddress((void**)&pWes, g_Wes);
    cudaGetSymbolAddress((void**)&pWfs, g_Wfs);
    cudaGetSymbolAddress((void**)&pA,   g_Aarr);
    cudaGetSymbolAddress((void**)&pB,   g_Barr);
    cudaGetSymbolAddress((void**)&pbc,  g_bc);
    cudaGetSymbolAddress((void**)&ph2,  g_h2);

    const int MB = (N_NODESC + 127) / 128;   // 391

    zero_init_kernel<<<(N_NODESC + 255) / 256, 256>>>();
    detect_kernel<<<256, 256>>>((const int*)ei);
    conv_hist_kernel<<<(N_EDGESC + 255) / 256, 256>>>(ei);
    scan1_kernel<<<SCAN_BLKS, 1024>>>();
    scan2_kernel<<<1, 64>>>();
    scan3_kernel<<<(N_NODESC + 255) / 256, 256>>>();
    scatter_kernel<<<(N_EDGESC + 255) / 256, 256>>>();

    prep_w_kernel<<<128, 256>>>(W_edge, b_edge, W_node, W_ed, W_f1);
    split_x_kernel<<<(N_NODESC * 64 + 255) / 256, 256>>>(x);

    // AB = x @ Wc  -> Aarr (bias folded) / Barr, fp32
    mma_gemm<128, 64, 32, 32, false, 2><<<dim3(8, MB), 256>>>(
        pxs, pWcs, pbc, pA, (u64*)0, pB, 0, 0, N_NODESC, 128, 512);

    aggregate_kernel<<<(N_NODESC + 7) / 8, 256>>>(x);

    // nodes -> h[:,0:256) split ; edges -> h[:,256:384) split
    mma_gemm<128, 64, 32, 32, true, 1><<<dim3(4, MB), 256>>>(
        pnas, pWns, b_node, (float*)0, phs, (float*)0, 192, 0, N_NODESC, 128, 256);
    mma_gemm<128, 64, 32, 32, true, 1><<<dim3(2, MB), 256>>>(
        peas, pWes, b_ed, (float*)0, phs, (float*)0, 192, 256, N_NODESC, 256, 128);

    // h2 = relu(h @ W_f1 + b_f1), fp32
    mma_gemm<128, 32, 32, 16, true, 0><<<dim3(1, MB), 256>>>(
        phs, pWfs, b_f1, ph2, (u64*)0, (float*)0, 32, 0, N_NODESC, 384, 32);

    sigmoid_kernel<<<(N_NODESC + 7) / 8, 256>>>(W_f2, b_f2, out);
}